// round 16
// baseline (speedup 1.0000x reference)
#include <cuda_runtime.h>
#include <math.h>

#define BB 64
#define TT 512
#define HH 512
#define GG 2048          // 4*H
#define RECBLK 128
#define RECTHR 256

// ---- static device scratch (no cudaMalloc allowed) ----
__device__ float g_G[67108864];    // G^T: [col 0..2048)[r=t*64+b 0..32768)  (268 MB)
__device__ float g_H0T[16777216];  // layer-0 output archive: [u][r]          (64 MB)
__device__ float g_h[65536];       // h state double buffer: 2 x [b][u]
__device__ unsigned g_cnt;         // monotonic arrival counter
__device__ unsigned g_gen;         // completed-barrier generation

// ---- L2-scope sync primitives (no L1 flush) ----
__device__ __forceinline__ unsigned atomAddRel(unsigned* p) {
    unsigned old;
    asm volatile("atom.release.gpu.global.add.u32 %0, [%1], 1;"
                 : "=r"(old) : "l"(p) : "memory");
    return old;
}
__device__ __forceinline__ unsigned ldAcq(const unsigned* p) {
    unsigned v;
    asm volatile("ld.acquire.gpu.global.u32 %0, [%1];"
                 : "=r"(v) : "l"(p) : "memory");
    return v;
}
__device__ __forceinline__ void stRel(unsigned* p, unsigned v) {
    asm volatile("st.release.gpu.global.u32 [%0], %1;"
                 :: "l"(p), "r"(v) : "memory");
}

// ---- single-level monotonic grid barrier (replay-safe: no resets) ----
__device__ __forceinline__ void gridBarrier() {
    __syncthreads();
    if (threadIdx.x == 0) {
        unsigned old = atomAddRel(&g_cnt);
        unsigned need = (old >> 7) + 1u;        // barrier index + 1
        if ((old & 127u) == 127u) {
            stRel(&g_gen, need);
        } else {
            while (ldAcq(&g_gen) < need) { }
        }
    }
    __syncthreads();
}

__device__ __forceinline__ float sigmoidf_(float x) {
    return 1.0f / (1.0f + __expf(-x));
}
// fast tanh via MUFU-based expf (rel err ~1e-6)
__device__ __forceinline__ float tanhf_(float x) {
    return 2.0f / (1.0f + __expf(-2.0f * x)) - 1.0f;
}

__device__ __forceinline__ unsigned smem_u32(const void* p) {
    unsigned a;
    asm("{ .reg .u64 t; cvta.to.shared.u64 t, %1; cvt.u32.u64 %0, t; }"
        : "=r"(a) : "l"(p));
    return a;
}

__device__ __forceinline__ void ldcg_u64x2(unsigned long long& a, unsigned long long& b,
                                           const void* p) {
    asm volatile("ld.global.cg.v2.u64 {%0,%1}, [%2];"
                 : "=l"(a), "=l"(b) : "l"(p));
}

// ============================================================
// Precompute GEMM (transposed output), FFMA2 inner loop (unchanged, passing):
//   Gt[col][r] = W[col][:] . Xrow(r)[:] + bih[col] + bhh[col]
//   M = col = 2048, N = r = 32768, K = 512.
// ============================================================
__global__ void __launch_bounds__(256) lstm_pregemm(
    const float* __restrict__ xin,
    const float* __restrict__ Wih,
    const float* __restrict__ bih,
    const float* __restrict__ bhh,
    int layer0)
{
    __shared__ __align__(16) float As[16][128];   // [k][m=col]
    __shared__ __align__(16) float Bs[16][128];   // [k][n=r]
    const int tid = threadIdx.x;
    const int rblk = blockIdx.x * 128;   // n
    const int mblk = blockIdx.y * 128;   // m (col)
    const int nx = tid & 15;
    const int mx = tid >> 4;

    unsigned long long acc[8][4];
    #pragma unroll
    for (int i = 0; i < 8; ++i)
        #pragma unroll
        for (int j = 0; j < 4; ++j) acc[i][j] = 0ull;

    const unsigned bsBase = smem_u32(Bs) + (unsigned)nx * 32u;

    for (int kc = 0; kc < 512; kc += 16) {
        #pragma unroll
        for (int jj = 0; jj < 2; ++jj) {
            int e = tid + jj * 256;
            int m = e >> 2;
            int kq = e & 3;
            float4 v = *(const float4*)(Wih + (size_t)(mblk + m) * 512 + kc + kq * 4);
            As[kq*4+0][m] = v.x; As[kq*4+1][m] = v.y;
            As[kq*4+2][m] = v.z; As[kq*4+3][m] = v.w;
        }
        if (layer0) {
            #pragma unroll
            for (int jj = 0; jj < 2; ++jj) {
                int e = tid + jj * 256;
                int n = e >> 2;
                int kq = e & 3;
                int r = rblk + n;
                const float* src = xin + (size_t)(((r & 63) << 9) + (r >> 6)) * 512;
                float4 v = *(const float4*)(src + kc + kq * 4);
                Bs[kq*4+0][n] = v.x; Bs[kq*4+1][n] = v.y;
                Bs[kq*4+2][n] = v.z; Bs[kq*4+3][n] = v.w;
            }
        } else {
            #pragma unroll
            for (int jj = 0; jj < 2; ++jj) {
                int e = tid + jj * 256;
                int k = e >> 5;
                int nq = e & 31;
                *(float4*)&Bs[k][nq * 4] =
                    *(const float4*)(g_H0T + (size_t)(kc + k) * 32768 + rblk + nq * 4);
            }
        }
        __syncthreads();
        #pragma unroll
        for (int k = 0; k < 16; ++k) {
            float a[8];
            *(float4*)(a)     = *(const float4*)&As[k][mx * 8];
            *(float4*)(a + 4) = *(const float4*)&As[k][mx * 8 + 4];
            unsigned long long b0, b1, b2, b3;
            unsigned ba = bsBase + (unsigned)k * 512u;
            asm("ld.shared.v2.u64 {%0,%1},[%2];" : "=l"(b0), "=l"(b1) : "r"(ba));
            asm("ld.shared.v2.u64 {%0,%1},[%2];" : "=l"(b2), "=l"(b3) : "r"(ba + 16u));
            #pragma unroll
            for (int i = 0; i < 8; ++i) {
                unsigned long long hh;
                asm("mov.b64 %0,{%1,%2};" : "=l"(hh) : "f"(a[i]), "f"(a[i]));
                asm("fma.rn.f32x2 %0,%1,%2,%0;" : "+l"(acc[i][0]) : "l"(hh), "l"(b0));
                asm("fma.rn.f32x2 %0,%1,%2,%0;" : "+l"(acc[i][1]) : "l"(hh), "l"(b1));
                asm("fma.rn.f32x2 %0,%1,%2,%0;" : "+l"(acc[i][2]) : "l"(hh), "l"(b2));
                asm("fma.rn.f32x2 %0,%1,%2,%0;" : "+l"(acc[i][3]) : "l"(hh), "l"(b3));
            }
        }
        __syncthreads();
    }

    #pragma unroll
    for (int i = 0; i < 8; ++i) {
        int col = mblk + mx * 8 + i;
        float bsum = bih[col] + bhh[col];
        float f[8];
        #pragma unroll
        for (int j = 0; j < 4; ++j)
            asm("mov.b64 {%0,%1},%2;" : "=f"(f[2*j]), "=f"(f[2*j+1]) : "l"(acc[i][j]));
        float* dst = g_G + (size_t)col * 32768 + rblk + nx * 8;
        float4 v0 = make_float4(f[0]+bsum, f[1]+bsum, f[2]+bsum, f[3]+bsum);
        float4 v1 = make_float4(f[4]+bsum, f[5]+bsum, f[6]+bsum, f[7]+bsum);
        *(float4*)dst = v0;
        *(float4*)(dst + 4) = v1;
    }
}

// ============================================================
// Persistent recurrent kernel v7: 128 CTAs x 256 threads.
// CTA j owns units u0=4j..4j+3 (16 gate-cols = 4 gates x 4 units).
// Thread = (bh = tid>>7, kr = (tid>>2)&31, cg = tid&3):
//   gate cg, units u0..u0+3, k in [kr*16, kr*16+16), b in [bh*32, bh*32+32).
// - h loaded as ld.global.cg.v2.u64: k-pairs land as 64-bit reg pairs,
//   fed DIRECTLY to fma.rn.f32x2 (zero packing movs).
// - Weights: 4 cols x 8 k-pairs in registers (32 u64), loaded once.
// - 6-slot fully-unrolled modular pipeline (no rotation movs), lookahead 6.
// - Split-K: v5's 2-round shfl-xor; red[8][64][18]; c state in registers.
// - Single-atomic monotonic grid barrier; G prefetched at loop top; fast tanh.
// ============================================================
__global__ void __launch_bounds__(RECTHR, 1) lstm_recurrent(
    const float* __restrict__ Whh,
    const float* __restrict__ h0,
    const float* __restrict__ c0,
    float* __restrict__ outSeq,   // layer1: [b][t][u]; layer0: null (writes g_H0T)
    float* __restrict__ hfin,
    float* __restrict__ cfin,
    int layer1)
{
    __shared__ __align__(16) float red[8][64][18];   // [s][b][col], col = gate*4+unit

    const int tid = threadIdx.x;
    const int bid = blockIdx.x;
    const int u0  = bid * 4;
    const int bh  = tid >> 7;            // b half
    const int kr  = (tid >> 2) & 31;     // k range index (16 k each)
    const int cg  = tid & 3;             // gate
    const int sIdx = kr >> 2;            // reduce slice 0..7
    const bool writer = ((tid & 12) == 0);   // kr % 4 == 0
    const int bC  = tid & 63;            // cell batch
    const int uu  = tid >> 6;            // cell unit offset

    // ---- persistent weights in registers as k-pairs ----
    // wk[c][kp] = { Whh[cg*512+u0+c][kr*16+2kp], Whh[...][kr*16+2kp+1] }
    unsigned long long wk[4][8];
    #pragma unroll
    for (int c = 0; c < 4; ++c) {
        const float2* wrow = (const float2*)(Whh + (size_t)(cg * 512 + u0 + c) * 512
                                                 + kr * 16);
        #pragma unroll
        for (int kp = 0; kp < 8; ++kp) {
            float2 v = wrow[kp];
            asm("mov.b64 %0,{%1,%2};" : "=l"(wk[c][kp]) : "f"(v.x), "f"(v.y));
        }
    }

    // init state
    {
        int idx = bid * RECTHR + tid;
        __stcg(&g_h[idx], h0[idx]);
    }
    float c_reg = c0[bC * HH + u0 + uu];

    const float* gPtr0 = g_G + (size_t)(0 * 512 + u0 + uu) * 32768 + bC;
    const float* gPtr1 = g_G + (size_t)(1 * 512 + u0 + uu) * 32768 + bC;
    const float* gPtr2 = g_G + (size_t)(2 * 512 + u0 + uu) * 32768 + bC;
    const float* gPtr3 = g_G + (size_t)(3 * 512 + u0 + uu) * 32768 + bC;

    gridBarrier();

    for (int t = 0; t < TT; ++t) {
        const float* hRead = g_h + (t & 1) * 32768;
        float* hWrite      = g_h + ((t + 1) & 1) * 32768;
        // u64-pair base for (b = bh*32 + bl): row stride = 512 floats = 256 u64
        // thread's k-slice starts at float kr*16 = u64 index kr*8
        const unsigned long long* hb =
            (const unsigned long long*)hRead + (size_t)(bh * 32) * 256 + kr * 8;

        // ---- prefetch this step's G values (hidden behind the GEMM) ----
        size_t go = (size_t)t * 64;
        float gpre0 = __ldcs(gPtr0 + go);
        float gpre1 = __ldcs(gPtr1 + go);
        float gpre2 = __ldcs(gPtr2 + go);
        float gpre3 = __ldcs(gPtr3 + go);

        // 6-slot buffer: each slot = 8 u64 = 16 k values of one b row
        unsigned long long buf[6][8];

        #define LD4(slot, bl) do {                                              \
            const unsigned long long* _p = hb + (size_t)(bl) * 256;             \
            ldcg_u64x2(buf[slot][0], buf[slot][1], _p);                         \
            ldcg_u64x2(buf[slot][2], buf[slot][3], _p + 2);                     \
            ldcg_u64x2(buf[slot][4], buf[slot][5], _p + 4);                     \
            ldcg_u64x2(buf[slot][6], buf[slot][7], _p + 6);                     \
        } while (0)

        #define COMP(slot, bl) do {                                             \
            unsigned long long _a0 = 0ull, _a1 = 0ull, _a2 = 0ull, _a3 = 0ull;  \
            _Pragma("unroll")                                                   \
            for (int _kp = 0; _kp < 8; ++_kp) {                                 \
                unsigned long long _hp = buf[slot][_kp];                        \
                asm("fma.rn.f32x2 %0,%1,%2,%0;" : "+l"(_a0) : "l"(_hp), "l"(wk[0][_kp])); \
                asm("fma.rn.f32x2 %0,%1,%2,%0;" : "+l"(_a1) : "l"(_hp), "l"(wk[1][_kp])); \
                asm("fma.rn.f32x2 %0,%1,%2,%0;" : "+l"(_a2) : "l"(_hp), "l"(wk[2][_kp])); \
                asm("fma.rn.f32x2 %0,%1,%2,%0;" : "+l"(_a3) : "l"(_hp), "l"(wk[3][_kp])); \
            }                                                                   \
            float _e, _o, _s0, _s1, _s2, _s3;                                   \
            asm("mov.b64 {%0,%1},%2;" : "=f"(_e), "=f"(_o) : "l"(_a0));         \
            _s0 = _e + _o;                                                      \
            asm("mov.b64 {%0,%1},%2;" : "=f"(_e), "=f"(_o) : "l"(_a1));         \
            _s1 = _e + _o;                                                      \
            asm("mov.b64 {%0,%1},%2;" : "=f"(_e), "=f"(_o) : "l"(_a2));         \
            _s2 = _e + _o;                                                      \
            asm("mov.b64 {%0,%1},%2;" : "=f"(_e), "=f"(_o) : "l"(_a3));         \
            _s3 = _e + _o;                                                      \
            _s0 += __shfl_xor_sync(0xffffffffu, _s0, 4);                        \
            _s1 += __shfl_xor_sync(0xffffffffu, _s1, 4);                        \
            _s2 += __shfl_xor_sync(0xffffffffu, _s2, 4);                        \
            _s3 += __shfl_xor_sync(0xffffffffu, _s3, 4);                        \
            _s0 += __shfl_xor_sync(0xffffffffu, _s0, 8);                        \
            _s1 += __shfl_xor_sync(0xffffffffu, _s1, 8);                        \
            _s2 += __shfl_xor_sync(0xffffffffu, _s2, 8);                        \
            _s3 += __shfl_xor_sync(0xffffffffu, _s3, 8);                        \
            if (writer) {                                                       \
                float* _r = &red[sIdx][bh * 32 + (bl)][cg * 4];                 \
                *(float2*)_r       = make_float2(_s0, _s1);                     \
                *(float2*)(_r + 2) = make_float2(_s2, _s3);                     \
            }                                                                   \
        } while (0)

        // prologue: fill 6 slots
        #pragma unroll
        for (int p = 0; p < 6; ++p) LD4(p, p);
        // fully-unrolled main loop: modular slot reuse, no rotation movs
        #pragma unroll
        for (int bl = 0; bl < 32; ++bl) {
            COMP(bl % 6, bl);
            if (bl + 6 < 32) LD4(bl % 6, bl + 6);
        }
        #undef LD4
        #undef COMP

        __syncthreads();

        // ---- cell update (thread owns (bC, u0+uu); c in register) ----
        {
            float v0 = gpre0, v1 = gpre1, v2 = gpre2, v3 = gpre3;
            #pragma unroll
            for (int s = 0; s < 8; ++s) {
                v0 += red[s][bC][0 * 4 + uu];
                v1 += red[s][bC][1 * 4 + uu];
                v2 += red[s][bC][2 * 4 + uu];
                v3 += red[s][bC][3 * 4 + uu];
            }
            float iv = sigmoidf_(v0);
            float fv = sigmoidf_(v1);
            float gv = tanhf_(v2);
            float ov = sigmoidf_(v3);
            c_reg = fv * c_reg + iv * gv;
            float hv = ov * tanhf_(c_reg);

            __stcg(&hWrite[bC * HH + u0 + uu], hv);
            if (layer1) outSeq[((size_t)bC * TT + t) * HH + u0 + uu] = hv;
            else        __stcg(&g_H0T[(size_t)(u0 + uu) * 32768 + (size_t)t * 64 + bC], hv);
            if (t == TT - 1) {
                hfin[bC * HH + u0 + uu] = hv;
                cfin[bC * HH + u0 + uu] = c_reg;
            }
        }
        gridBarrier();
    }
}

// ============================================================
// kernel_launch: 4 graph-capturable launches.
// Output: out [B,T,H] ++ h_fin [2,B,H] ++ c_fin [2,B,H]
// ============================================================
extern "C" void kernel_launch(void* const* d_in, const int* in_sizes, int n_in,
                              void* d_out, int out_size)
{
    (void)in_sizes; (void)n_in; (void)out_size;
    const float* x   = (const float*)d_in[0];
    const float* h0  = (const float*)d_in[1];
    const float* c0  = (const float*)d_in[2];
    const float* Wih = (const float*)d_in[3];
    const float* Whh = (const float*)d_in[4];
    const float* bih = (const float*)d_in[5];
    const float* bhh = (const float*)d_in[6];
    float* out  = (float*)d_out;
    float* hfin = out + (size_t)BB * TT * HH;
    float* cfin = hfin + 2 * BB * HH;

    dim3 pgrid(32768 / 128, GG / 128);   // (256, 16)

    // layer 0
    lstm_pregemm<<<pgrid, 256>>>(x, Wih, bih, bhh, 1);
    lstm_recurrent<<<RECBLK, RECTHR>>>(Whh, h0, c0, nullptr, hfin, cfin, 0);
    // layer 1 (input GEMM reads g_H0T directly)
    lstm_pregemm<<<pgrid, 256>>>(x, Wih + (size_t)GG * 512, bih + GG, bhh + GG, 0);
    lstm_recurrent<<<RECBLK, RECTHR>>>(Whh + (size_t)GG * 512,
                                       h0 + BB * HH, c0 + BB * HH,
                                       out, hfin + BB * HH, cfin + BB * HH, 1);
}